// round 11
// baseline (speedup 1.0000x reference)
#include <cuda_runtime.h>

// Problem: x [B=8, C=64, H=64, W=64], N = H*W = 4096
// out = [ y (B*C*N fp32) | attn (B*N*N fp32) ]
#define BATCH 8
#define CDIM  64
#define NDIM  4096
#define NN    (NDIM * NDIM)
#define Y_ELEMS (BATCH * CDIM * NDIM)

typedef unsigned long long ull;

// ---------------------------------------------------------------------------
// Packed f32x2 (sm_103a FFMA2 — 2x fp32 FMA throughput, PTX-only)
// ---------------------------------------------------------------------------
__device__ __forceinline__ void unpack2(float& lo, float& hi, ull v) {
    asm("mov.b64 {%0, %1}, %2;" : "=f"(lo), "=f"(hi) : "l"(v));
}
__device__ __forceinline__ void ffma2(ull& d, ull a, ull b) {
    asm("fma.rn.f32x2 %0, %1, %2, %0;" : "+l"(d) : "l"(a), "l"(b));
}

// ---------------------------------------------------------------------------
// K1: raw scores S[b][n][m] = sum_c x[b][c][n] * x[b][c][m]
// 128x128 tile per CTA, 512 threads (16x32), per-thread 4 rows x 4 col-pairs.
// Q stored DUPLICATED in smem so the dup'd FFMA2 operand is one broadcast
// LDS.64 (no packs). Inner loop: 4+4 LDS.64 + 16 FFMA2 = 24 instr, 67% fma.
// occ 2 => 32 warps/SM = 8/SMSP (vs 4 before) for latency hiding.
// ---------------------------------------------------------------------------
__global__ __launch_bounds__(512, 2)
void scores_kernel(const float* __restrict__ x, float* __restrict__ attn) {
    __shared__ float Qd[32][256];   // Q chunk, each value duplicated: (q,q)
    __shared__ float Ks[32][128];   // K chunk

    const int t  = threadIdx.x;
    const int tx = t & 15;          // col group: cols 2*tx + 32*u
    const int ty = t >> 4;          // 0..31, rows ty + 32*i
    const int m0 = blockIdx.x * 128;
    const int n0 = blockIdx.y * 128;
    const int b  = blockIdx.z;
    const float* xb = x + (size_t)b * (CDIM * NDIM);

    ull acc[4][4];
#pragma unroll
    for (int i = 0; i < 4; i++)
#pragma unroll
        for (int u = 0; u < 4; u++) acc[i][u] = 0ULL;

    for (int cc = 0; cc < CDIM; cc += 32) {
        // 512 threads load 32x128 Q (dup-stored) and 32x128 K. Coalesced.
#pragma unroll
        for (int k = 0; k < 8; k++) {
            int idx = t + k * 512;           // 0..4095
            int cl  = idx >> 7;
            int j   = idx & 127;
            float q = xb[(cc + cl) * NDIM + n0 + j];
            *(float2*)&Qd[cl][2 * j] = make_float2(q, q);  // 8B-strided STS.64
            Ks[cl][j] = xb[(cc + cl) * NDIM + m0 + j];
        }
        __syncthreads();

#pragma unroll
        for (int cl = 0; cl < 32; cl++) {
            ull b2[4];
#pragma unroll
            for (int u = 0; u < 4; u++)      // lanes 8B apart: conflict-free
                b2[u] = *(const ull*)&Ks[cl][2 * tx + 32 * u];
#pragma unroll
            for (int i = 0; i < 4; i++) {
                // (a,a) directly from dup'd smem — broadcast LDS.64, no pack
                ull a2 = *(const ull*)&Qd[cl][2 * (ty + 32 * i)];
#pragma unroll
                for (int u = 0; u < 4; u++) ffma2(acc[i][u], a2, b2[u]);
            }
        }
        __syncthreads();
    }

    float* arow = attn + (size_t)b * NN;
#pragma unroll
    for (int i = 0; i < 4; i++) {
        size_t base = (size_t)(n0 + ty + 32 * i) * NDIM + m0;
#pragma unroll
        for (int u = 0; u < 4; u++) {
            float lo, hi;
            unpack2(lo, hi, acc[i][u]);
            *(float2*)&arow[base + 2 * tx + 32 * u] = make_float2(lo, hi);
        }
    }
}

// ---------------------------------------------------------------------------
// K2: in-place row softmax (unchanged from the 1127us kernel — proven).
// One 128-thread block per (b, n) row; row register-resident.
// ---------------------------------------------------------------------------
__global__ __launch_bounds__(128)
void softmax_kernel(float* __restrict__ attn) {
    const int n = blockIdx.x;
    const int b = blockIdx.y;
    float4* row = (float4*)(attn + (size_t)b * NN + (size_t)n * NDIM);
    const int t = threadIdx.x;

    float4 v[8];
    float m = -1e30f;
#pragma unroll
    for (int k = 0; k < 8; k++) {
        v[k] = row[t + 128 * k];
        m = fmaxf(m, fmaxf(fmaxf(v[k].x, v[k].y), fmaxf(v[k].z, v[k].w)));
    }
#pragma unroll
    for (int o = 16; o > 0; o >>= 1)
        m = fmaxf(m, __shfl_xor_sync(0xffffffffu, m, o));

    __shared__ float smax[4];
    __shared__ float ssum[4];
    const int warp = t >> 5, lane = t & 31;
    if (lane == 0) smax[warp] = m;
    __syncthreads();
    m = fmaxf(fmaxf(smax[0], smax[1]), fmaxf(smax[2], smax[3]));

    float s = 0.0f;
#pragma unroll
    for (int k = 0; k < 8; k++) {
        v[k].x = __expf(v[k].x - m);
        v[k].y = __expf(v[k].y - m);
        v[k].z = __expf(v[k].z - m);
        v[k].w = __expf(v[k].w - m);
        s += (v[k].x + v[k].y) + (v[k].z + v[k].w);
    }
#pragma unroll
    for (int o = 16; o > 0; o >>= 1)
        s += __shfl_xor_sync(0xffffffffu, s, o);
    if (lane == 0) ssum[warp] = s;
    __syncthreads();
    s = (ssum[0] + ssum[1]) + (ssum[2] + ssum[3]);

    const float inv = 1.0f / s;
#pragma unroll
    for (int k = 0; k < 8; k++) {
        v[k].x *= inv; v[k].y *= inv; v[k].z *= inv; v[k].w *= inv;
        row[t + 128 * k] = v[k];
    }
}

// ---------------------------------------------------------------------------
// K3: y[b][c][n] = sum_m attn[b][n][m] * x[b][c][m]
// 128 n-rows x 64 c per CTA, 256 threads; m in chunks of 32.
// X stored DUPLICATED in smem (Xd[m][2c]=(v,v)): inner loop 4+4 LDS.64 +
// 16 FFMA2 = 24 instr (was 28 with packs). No attn writes here.
// ---------------------------------------------------------------------------
__global__ __launch_bounds__(256, 2)
void av_kernel(const float* __restrict__ x, const float* __restrict__ attn,
               float* __restrict__ y) {
    __shared__ float As[32][130];   // attn tile transposed: As[m][n-row]
    __shared__ float Xd[32][130];   // X tile, c duplicated: Xd[m][2c]=(v,v)

    const int t  = threadIdx.x;
    const int tx = t & 15;          // cols c = tx + 16*u
    const int ty = t >> 4;          // row pairs 2*ty + 32*i
    const int n0 = blockIdx.x * 128;
    const int b  = blockIdx.y;
    const float* xb = x + (size_t)b * (CDIM * NDIM);
    const float* ab = attn + (size_t)b * NN;

    ull acc[4][4];
#pragma unroll
    for (int i = 0; i < 4; i++)
#pragma unroll
        for (int u = 0; u < 4; u++) acc[i][u] = 0ULL;

    for (int m0 = 0; m0 < NDIM; m0 += 32) {
        // As[j][r] = attn[n0+r][m0+j] : coalesced LDG, 2-way STS (pitch 130)
#pragma unroll
        for (int kk = 0; kk < 16; kk++) {
            int idx = t + kk * 256;
            int r = idx >> 5;
            int j = idx & 31;
            As[j][r] = ab[(size_t)(n0 + r) * NDIM + m0 + j];
        }
        // Xd[j][2c] = dup of x[c][m0+j] : coalesced LDG, 8B STS
#pragma unroll
        for (int kk = 0; kk < 8; kk++) {
            int idx = t + kk * 256;
            int c = idx >> 5;
            int j = idx & 31;
            float v = xb[c * NDIM + m0 + j];
            *(float2*)&Xd[j][2 * c] = make_float2(v, v);
        }
        __syncthreads();

#pragma unroll
        for (int mm = 0; mm < 32; mm++) {
            ull a2[4];
#pragma unroll
            for (int i = 0; i < 4; i++)   // 8B-aligned n-row pairs
                a2[i] = *(const ull*)&As[mm][2 * ty + 32 * i];
#pragma unroll
            for (int u = 0; u < 4; u++) {
                // dup'd (v,v) directly from smem — 8B-strided, no pack
                ull b2 = *(const ull*)&Xd[mm][2 * (tx + 16 * u)];
#pragma unroll
                for (int i = 0; i < 4; i++) ffma2(acc[i][u], a2[i], b2);
            }
        }
        __syncthreads();
    }

#pragma unroll
    for (int u = 0; u < 4; u++) {
        int c = tx + 16 * u;
#pragma unroll
        for (int i = 0; i < 4; i++) {
            float lo, hi;
            unpack2(lo, hi, acc[i][u]);
            int n = n0 + 2 * ty + 32 * i;
            *(float2*)&y[(size_t)b * (CDIM * NDIM) + (size_t)c * NDIM + n] =
                make_float2(lo, hi);
        }
    }
}

// ---------------------------------------------------------------------------
// Launch. d_in[0] = x. d_out = [ y | attn ]. Graph-capturable, alloc-free.
// ---------------------------------------------------------------------------
extern "C" void kernel_launch(void* const* d_in, const int* in_sizes, int n_in,
                              void* d_out, int out_size) {
    (void)in_sizes; (void)n_in; (void)out_size;
    const float* x = (const float*)d_in[0];
    float* out  = (float*)d_out;
    float* y    = out;
    float* attn = out + Y_ELEMS;

    dim3 g1(NDIM / 128, NDIM / 128, BATCH);   // (32, 32, 8)
    scores_kernel<<<g1, 512>>>(x, attn);

    dim3 g2(NDIM, BATCH);                     // (4096, 8)
    softmax_kernel<<<g2, 128>>>(attn);

    dim3 g3(NDIM / 128, BATCH);               // (32, 8): one wave @ occ 2
    av_kernel<<<g3, 256>>>(x, attn, y);
}

// round 13
// speedup vs baseline: 1.1351x; 1.1351x over previous
#include <cuda_runtime.h>

// Problem: x [B=8, C=64, H=64, W=64], N = H*W = 4096
// out = [ y (B*C*N fp32) | attn (B*N*N fp32) ]
#define BATCH 8
#define CDIM  64
#define NDIM  4096
#define NN    (NDIM * NDIM)
#define Y_ELEMS (BATCH * CDIM * NDIM)

typedef unsigned long long ull;

// ---------------------------------------------------------------------------
// Packed f32x2 (sm_103a FFMA2 — 2x fp32 FMA throughput, PTX-only)
// ---------------------------------------------------------------------------
__device__ __forceinline__ ull pack2(float lo, float hi) {
    ull r; asm("mov.b64 %0, {%1, %2};" : "=l"(r) : "f"(lo), "f"(hi)); return r;
}
__device__ __forceinline__ void unpack2(float& lo, float& hi, ull v) {
    asm("mov.b64 {%0, %1}, %2;" : "=f"(lo), "=f"(hi) : "l"(v));
}
__device__ __forceinline__ void ffma2(ull& d, ull a, ull b) {
    asm("fma.rn.f32x2 %0, %1, %2, %0;" : "+l"(d) : "l"(a), "l"(b));
}

// ---------------------------------------------------------------------------
// K1: raw scores S[b][n][m] = sum_c x[b][c][n] * x[b][c][m]
// 128x128 tile, 256 threads (16x16), per-thread 8 rows x 8 cols.
// LDS budget per cl per thread: 2 LDS.128 (Ks: 8 cols = 4 reg-adjacent f32x2
// pairs) + 4 LDS.128 (Qd dup'd: 2 duplicated row-operands each) = 6 LDS for
// 32 FFMA2. Crossbar wavefronts/warp/cl: 8 vs 64 fma-pipe cycles -> fma-bound.
// ---------------------------------------------------------------------------
__global__ __launch_bounds__(256, 2)
void scores_kernel(const float* __restrict__ x, float* __restrict__ attn) {
    __shared__ float Qd[32][256];   // Q chunk duplicated: Qd[cl][2r]=(q,q)
    __shared__ float Ks[32][128];   // K chunk

    const int t  = threadIdx.x;
    const int tx = t & 15;          // cols: 4*tx + 64*u + {0..3}
    const int ty = t >> 4;          // rows: 4*ty + 64*v + {0..3}
    const int m0 = blockIdx.x * 128;
    const int n0 = blockIdx.y * 128;
    const int b  = blockIdx.z;
    const float* xb = x + (size_t)b * (CDIM * NDIM);

    ull acc[2][4][2][2];            // [v][rr][u][pair]
#pragma unroll
    for (int v = 0; v < 2; v++)
#pragma unroll
        for (int rr = 0; rr < 4; rr++)
#pragma unroll
            for (int u = 0; u < 2; u++) {
                acc[v][rr][u][0] = 0ULL;
                acc[v][rr][u][1] = 0ULL;
            }

    for (int cc = 0; cc < CDIM; cc += 32) {
        // 256 threads load 32x128 Q (dup-stored) + 32x128 K. Coalesced LDG.
#pragma unroll
        for (int k = 0; k < 16; k++) {
            int idx = t + k * 256;           // 0..4095
            int cl  = idx >> 7;
            int j   = idx & 127;
            float q = xb[(cc + cl) * NDIM + n0 + j];
            *(float2*)&Qd[cl][2 * j] = make_float2(q, q);
            Ks[cl][j] = xb[(cc + cl) * NDIM + m0 + j];
        }
        __syncthreads();

#pragma unroll
        for (int cl = 0; cl < 32; cl++) {
            // b-side: 8 cols as 2 LDS.128 -> 4 f32x2 pairs (reg-adjacent)
            float4 kv0 = *(const float4*)&Ks[cl][4 * tx];
            float4 kv1 = *(const float4*)&Ks[cl][4 * tx + 64];
            const ull* k0 = (const ull*)&kv0;
            const ull* k1 = (const ull*)&kv1;
#pragma unroll
            for (int v = 0; v < 2; v++) {
#pragma unroll
                for (int rp = 0; rp < 2; rp++) {
                    // a-side: LDS.128 on dup'd Qd -> 2 duplicated row operands
                    float4 qv = *(const float4*)&Qd[cl][8 * ty + 128 * v + 4 * rp];
                    const ull* qq = (const ull*)&qv;
#pragma unroll
                    for (int h = 0; h < 2; h++) {
                        int rr = 2 * rp + h;
                        ffma2(acc[v][rr][0][0], qq[h], k0[0]);
                        ffma2(acc[v][rr][0][1], qq[h], k0[1]);
                        ffma2(acc[v][rr][1][0], qq[h], k1[0]);
                        ffma2(acc[v][rr][1][1], qq[h], k1[1]);
                    }
                }
            }
        }
        __syncthreads();
    }

    float* arow = attn + (size_t)b * NN;
#pragma unroll
    for (int v = 0; v < 2; v++)
#pragma unroll
        for (int rr = 0; rr < 4; rr++) {
            int r = 4 * ty + 64 * v + rr;
            size_t base = (size_t)(n0 + r) * NDIM + m0;
#pragma unroll
            for (int u = 0; u < 2; u++) {
                float4 o;
                unpack2(o.x, o.y, acc[v][rr][u][0]);
                unpack2(o.z, o.w, acc[v][rr][u][1]);
                *(float4*)&arow[base + 4 * tx + 64 * u] = o;  // STG.128
            }
        }
}

// ---------------------------------------------------------------------------
// K2: in-place row softmax (proven, near streaming limit). Unchanged.
// ---------------------------------------------------------------------------
__global__ __launch_bounds__(128)
void softmax_kernel(float* __restrict__ attn) {
    const int n = blockIdx.x;
    const int b = blockIdx.y;
    float4* row = (float4*)(attn + (size_t)b * NN + (size_t)n * NDIM);
    const int t = threadIdx.x;

    float4 v[8];
    float m = -1e30f;
#pragma unroll
    for (int k = 0; k < 8; k++) {
        v[k] = row[t + 128 * k];
        m = fmaxf(m, fmaxf(fmaxf(v[k].x, v[k].y), fmaxf(v[k].z, v[k].w)));
    }
#pragma unroll
    for (int o = 16; o > 0; o >>= 1)
        m = fmaxf(m, __shfl_xor_sync(0xffffffffu, m, o));

    __shared__ float smax[4];
    __shared__ float ssum[4];
    const int warp = t >> 5, lane = t & 31;
    if (lane == 0) smax[warp] = m;
    __syncthreads();
    m = fmaxf(fmaxf(smax[0], smax[1]), fmaxf(smax[2], smax[3]));

    float s = 0.0f;
#pragma unroll
    for (int k = 0; k < 8; k++) {
        v[k].x = __expf(v[k].x - m);
        v[k].y = __expf(v[k].y - m);
        v[k].z = __expf(v[k].z - m);
        v[k].w = __expf(v[k].w - m);
        s += (v[k].x + v[k].y) + (v[k].z + v[k].w);
    }
#pragma unroll
    for (int o = 16; o > 0; o >>= 1)
        s += __shfl_xor_sync(0xffffffffu, s, o);
    if (lane == 0) ssum[warp] = s;
    __syncthreads();
    s = (ssum[0] + ssum[1]) + (ssum[2] + ssum[3]);

    const float inv = 1.0f / s;
#pragma unroll
    for (int k = 0; k < 8; k++) {
        v[k].x *= inv; v[k].y *= inv; v[k].z *= inv; v[k].w *= inv;
        row[t + 128 * k] = v[k];
    }
}

// ---------------------------------------------------------------------------
// K3: y[b][c][n] = sum_m attn[b][n][m] * x[b][c][m]
// 128 n x 64 c per CTA, 256 threads; per-thread 4 n-pairs x 4 c.
// X stored c-major Xt[c][m] (pitch 36 = 16B-aligned rows, conflict-free STS);
// each thread preloads its 4 c x 8 m into registers (LDS.128, broadcast wf),
// duplicates on the idle ALU pipe via pack2. LDS wf/mm drops 8 -> ~5.
// ---------------------------------------------------------------------------
__global__ __launch_bounds__(256, 2)
void av_kernel(const float* __restrict__ x, const float* __restrict__ attn,
               float* __restrict__ y) {
    __shared__ float As[32][130];   // attn tile transposed: As[m][n-row]
    __shared__ float Xt[64][36];    // X tile c-major: Xt[c][m]

    const int t  = threadIdx.x;
    const int tx = t & 15;          // n-pairs: 2*tx + 32*i
    const int ty = t >> 4;          // c: 4*ty + cc
    const int n0 = blockIdx.x * 128;
    const int b  = blockIdx.y;
    const float* xb = x + (size_t)b * (CDIM * NDIM);
    const float* ab = attn + (size_t)b * NN;

    ull acc[4][4];                  // [i: n-pair][cc: c]
#pragma unroll
    for (int i = 0; i < 4; i++)
#pragma unroll
        for (int cc = 0; cc < 4; cc++) acc[i][cc] = 0ULL;

    for (int m0 = 0; m0 < NDIM; m0 += 32) {
        // As[j][r] = attn[n0+r][m0+j] : coalesced LDG, mild STS conflict
#pragma unroll
        for (int kk = 0; kk < 16; kk++) {
            int idx = t + kk * 256;
            int r = idx >> 5;
            int j = idx & 31;
            As[j][r] = ab[(size_t)(n0 + r) * NDIM + m0 + j];
        }
        // Xt[c][j] = x[c][m0+j] : coalesced LDG, conflict-free STS (stride 1)
#pragma unroll
        for (int kk = 0; kk < 8; kk++) {
            int idx = t + kk * 256;
            int c = idx >> 5;
            int j = idx & 31;
            Xt[c][j] = xb[c * NDIM + m0 + j];
        }
        __syncthreads();

#pragma unroll
        for (int ms = 0; ms < 4; ms++) {        // 4 segments of 8 m
            // Preload this thread's 4 c-rows x 8 m into registers.
            float4 xr[4][2];
#pragma unroll
            for (int cc = 0; cc < 4; cc++) {
                xr[cc][0] = *(const float4*)&Xt[4 * ty + cc][8 * ms];
                xr[cc][1] = *(const float4*)&Xt[4 * ty + cc][8 * ms + 4];
            }
#pragma unroll
            for (int m2 = 0; m2 < 8; m2++) {
                int mm = 8 * ms + m2;
                ull a2[4];
#pragma unroll
                for (int i = 0; i < 4; i++)     // 8B-strided lanes: 1 wf each
                    a2[i] = *(const ull*)&As[mm][2 * tx + 32 * i];
#pragma unroll
                for (int cc = 0; cc < 4; cc++) {
                    const float* xf = (const float*)&xr[cc][m2 >> 2];
                    float xv = xf[m2 & 3];
                    ull b2 = pack2(xv, xv);     // ALU pipe (idle)
#pragma unroll
                    for (int i = 0; i < 4; i++) ffma2(acc[i][cc], a2[i], b2);
                }
            }
        }
        __syncthreads();
    }

#pragma unroll
    for (int cc = 0; cc < 4; cc++) {
        int c = 4 * ty + cc;
#pragma unroll
        for (int i = 0; i < 4; i++) {
            float lo, hi;
            unpack2(lo, hi, acc[i][cc]);
            int n = n0 + 2 * tx + 32 * i;
            *(float2*)&y[(size_t)b * (CDIM * NDIM) + (size_t)c * NDIM + n] =
                make_float2(lo, hi);
        }
    }
}

// ---------------------------------------------------------------------------
// Launch. d_in[0] = x. d_out = [ y | attn ]. Graph-capturable, alloc-free.
// ---------------------------------------------------------------------------
extern "C" void kernel_launch(void* const* d_in, const int* in_sizes, int n_in,
                              void* d_out, int out_size) {
    (void)in_sizes; (void)n_in; (void)out_size;
    const float* x = (const float*)d_in[0];
    float* out  = (float*)d_out;
    float* y    = out;
    float* attn = out + Y_ELEMS;

    dim3 g1(NDIM / 128, NDIM / 128, BATCH);   // (32, 32, 8)
    scores_kernel<<<g1, 256>>>(x, attn);

    dim3 g2(NDIM, BATCH);                     // (4096, 8)
    softmax_kernel<<<g2, 128>>>(attn);

    dim3 g3(NDIM / 128, BATCH);               // (32, 8): ~one wave @ occ 2
    av_kernel<<<g3, 256>>>(x, attn, y);
}

// round 14
// speedup vs baseline: 1.1353x; 1.0001x over previous
#include <cuda_runtime.h>

// Problem: x [B=8, C=64, H=64, W=64], N = H*W = 4096
// out = [ y (B*C*N fp32) | attn (B*N*N fp32) ]
#define BATCH 8
#define CDIM  64
#define NDIM  4096
#define NN    (NDIM * NDIM)
#define Y_ELEMS (BATCH * CDIM * NDIM)

typedef unsigned long long ull;

// ---------------------------------------------------------------------------
// Packed f32x2 (sm_103a FFMA2 — 2x fp32 FMA throughput, PTX-only)
// ---------------------------------------------------------------------------
__device__ __forceinline__ ull pack2(float lo, float hi) {
    ull r; asm("mov.b64 %0, {%1, %2};" : "=l"(r) : "f"(lo), "f"(hi)); return r;
}
__device__ __forceinline__ void unpack2(float& lo, float& hi, ull v) {
    asm("mov.b64 {%0, %1}, %2;" : "=f"(lo), "=f"(hi) : "l"(v));
}
__device__ __forceinline__ void ffma2(ull& d, ull a, ull b) {
    asm("fma.rn.f32x2 %0, %1, %2, %0;" : "+l"(d) : "l"(a), "l"(b));
}

// ---------------------------------------------------------------------------
// K1: raw scores S[b][n][m] = sum_c x[b][c][n] * x[b][c][m]
// 128x128 tile, 256 threads (16x16), per-thread 8 rows x 8 cols.
// LDS budget per cl per thread: 2 LDS.128 (Ks: 8 cols = 4 reg-adjacent f32x2
// pairs) + 4 LDS.128 (Qd dup'd: 2 duplicated row-operands each) = 6 LDS for
// 32 FFMA2. Crossbar wavefronts/warp/cl: 8 vs 64 fma-pipe cycles -> fma-bound.
// ---------------------------------------------------------------------------
__global__ __launch_bounds__(256, 2)
void scores_kernel(const float* __restrict__ x, float* __restrict__ attn) {
    __shared__ float Qd[32][256];   // Q chunk duplicated: Qd[cl][2r]=(q,q)
    __shared__ float Ks[32][128];   // K chunk

    const int t  = threadIdx.x;
    const int tx = t & 15;          // cols: 4*tx + 64*u + {0..3}
    const int ty = t >> 4;          // rows: 4*ty + 64*v + {0..3}
    const int m0 = blockIdx.x * 128;
    const int n0 = blockIdx.y * 128;
    const int b  = blockIdx.z;
    const float* xb = x + (size_t)b * (CDIM * NDIM);

    ull acc[2][4][2][2];            // [v][rr][u][pair]
#pragma unroll
    for (int v = 0; v < 2; v++)
#pragma unroll
        for (int rr = 0; rr < 4; rr++)
#pragma unroll
            for (int u = 0; u < 2; u++) {
                acc[v][rr][u][0] = 0ULL;
                acc[v][rr][u][1] = 0ULL;
            }

    for (int cc = 0; cc < CDIM; cc += 32) {
        // 256 threads load 32x128 Q (dup-stored) + 32x128 K. Coalesced LDG.
#pragma unroll
        for (int k = 0; k < 16; k++) {
            int idx = t + k * 256;           // 0..4095
            int cl  = idx >> 7;
            int j   = idx & 127;
            float q = xb[(cc + cl) * NDIM + n0 + j];
            *(float2*)&Qd[cl][2 * j] = make_float2(q, q);
            Ks[cl][j] = xb[(cc + cl) * NDIM + m0 + j];
        }
        __syncthreads();

#pragma unroll
        for (int cl = 0; cl < 32; cl++) {
            // b-side: 8 cols as 2 LDS.128 -> 4 f32x2 pairs (reg-adjacent)
            float4 kv0 = *(const float4*)&Ks[cl][4 * tx];
            float4 kv1 = *(const float4*)&Ks[cl][4 * tx + 64];
            const ull* k0 = (const ull*)&kv0;
            const ull* k1 = (const ull*)&kv1;
#pragma unroll
            for (int v = 0; v < 2; v++) {
#pragma unroll
                for (int rp = 0; rp < 2; rp++) {
                    // a-side: LDS.128 on dup'd Qd -> 2 duplicated row operands
                    float4 qv = *(const float4*)&Qd[cl][8 * ty + 128 * v + 4 * rp];
                    const ull* qq = (const ull*)&qv;
#pragma unroll
                    for (int h = 0; h < 2; h++) {
                        int rr = 2 * rp + h;
                        ffma2(acc[v][rr][0][0], qq[h], k0[0]);
                        ffma2(acc[v][rr][0][1], qq[h], k0[1]);
                        ffma2(acc[v][rr][1][0], qq[h], k1[0]);
                        ffma2(acc[v][rr][1][1], qq[h], k1[1]);
                    }
                }
            }
        }
        __syncthreads();
    }

    float* arow = attn + (size_t)b * NN;
#pragma unroll
    for (int v = 0; v < 2; v++)
#pragma unroll
        for (int rr = 0; rr < 4; rr++) {
            int r = 4 * ty + 64 * v + rr;
            size_t base = (size_t)(n0 + r) * NDIM + m0;
#pragma unroll
            for (int u = 0; u < 2; u++) {
                float4 o;
                unpack2(o.x, o.y, acc[v][rr][u][0]);
                unpack2(o.z, o.w, acc[v][rr][u][1]);
                *(float4*)&arow[base + 4 * tx + 64 * u] = o;  // STG.128
            }
        }
}

// ---------------------------------------------------------------------------
// K2: in-place row softmax (proven, near streaming limit). Unchanged.
// ---------------------------------------------------------------------------
__global__ __launch_bounds__(128)
void softmax_kernel(float* __restrict__ attn) {
    const int n = blockIdx.x;
    const int b = blockIdx.y;
    float4* row = (float4*)(attn + (size_t)b * NN + (size_t)n * NDIM);
    const int t = threadIdx.x;

    float4 v[8];
    float m = -1e30f;
#pragma unroll
    for (int k = 0; k < 8; k++) {
        v[k] = row[t + 128 * k];
        m = fmaxf(m, fmaxf(fmaxf(v[k].x, v[k].y), fmaxf(v[k].z, v[k].w)));
    }
#pragma unroll
    for (int o = 16; o > 0; o >>= 1)
        m = fmaxf(m, __shfl_xor_sync(0xffffffffu, m, o));

    __shared__ float smax[4];
    __shared__ float ssum[4];
    const int warp = t >> 5, lane = t & 31;
    if (lane == 0) smax[warp] = m;
    __syncthreads();
    m = fmaxf(fmaxf(smax[0], smax[1]), fmaxf(smax[2], smax[3]));

    float s = 0.0f;
#pragma unroll
    for (int k = 0; k < 8; k++) {
        v[k].x = __expf(v[k].x - m);
        v[k].y = __expf(v[k].y - m);
        v[k].z = __expf(v[k].z - m);
        v[k].w = __expf(v[k].w - m);
        s += (v[k].x + v[k].y) + (v[k].z + v[k].w);
    }
#pragma unroll
    for (int o = 16; o > 0; o >>= 1)
        s += __shfl_xor_sync(0xffffffffu, s, o);
    if (lane == 0) ssum[warp] = s;
    __syncthreads();
    s = (ssum[0] + ssum[1]) + (ssum[2] + ssum[3]);

    const float inv = 1.0f / s;
#pragma unroll
    for (int k = 0; k < 8; k++) {
        v[k].x *= inv; v[k].y *= inv; v[k].z *= inv; v[k].w *= inv;
        row[t + 128 * k] = v[k];
    }
}

// ---------------------------------------------------------------------------
// K3: y[b][c][n] = sum_m attn[b][n][m] * x[b][c][m]
// 128 n x 64 c per CTA, 256 threads; per-thread 4 n-pairs x 4 c.
// X stored c-major Xt[c][m] (pitch 36 = 16B-aligned rows, conflict-free STS);
// each thread preloads its 4 c x 8 m into registers (LDS.128, broadcast wf),
// duplicates on the idle ALU pipe via pack2. LDS wf/mm drops 8 -> ~5.
// ---------------------------------------------------------------------------
__global__ __launch_bounds__(256, 2)
void av_kernel(const float* __restrict__ x, const float* __restrict__ attn,
               float* __restrict__ y) {
    __shared__ float As[32][130];   // attn tile transposed: As[m][n-row]
    __shared__ float Xt[64][36];    // X tile c-major: Xt[c][m]

    const int t  = threadIdx.x;
    const int tx = t & 15;          // n-pairs: 2*tx + 32*i
    const int ty = t >> 4;          // c: 4*ty + cc
    const int n0 = blockIdx.x * 128;
    const int b  = blockIdx.y;
    const float* xb = x + (size_t)b * (CDIM * NDIM);
    const float* ab = attn + (size_t)b * NN;

    ull acc[4][4];                  // [i: n-pair][cc: c]
#pragma unroll
    for (int i = 0; i < 4; i++)
#pragma unroll
        for (int cc = 0; cc < 4; cc++) acc[i][cc] = 0ULL;

    for (int m0 = 0; m0 < NDIM; m0 += 32) {
        // As[j][r] = attn[n0+r][m0+j] : coalesced LDG, mild STS conflict
#pragma unroll
        for (int kk = 0; kk < 16; kk++) {
            int idx = t + kk * 256;
            int r = idx >> 5;
            int j = idx & 31;
            As[j][r] = ab[(size_t)(n0 + r) * NDIM + m0 + j];
        }
        // Xt[c][j] = x[c][m0+j] : coalesced LDG, conflict-free STS (stride 1)
#pragma unroll
        for (int kk = 0; kk < 8; kk++) {
            int idx = t + kk * 256;
            int c = idx >> 5;
            int j = idx & 31;
            Xt[c][j] = xb[c * NDIM + m0 + j];
        }
        __syncthreads();

#pragma unroll
        for (int ms = 0; ms < 4; ms++) {        // 4 segments of 8 m
            // Preload this thread's 4 c-rows x 8 m into registers.
            float4 xr[4][2];
#pragma unroll
            for (int cc = 0; cc < 4; cc++) {
                xr[cc][0] = *(const float4*)&Xt[4 * ty + cc][8 * ms];
                xr[cc][1] = *(const float4*)&Xt[4 * ty + cc][8 * ms + 4];
            }
#pragma unroll
            for (int m2 = 0; m2 < 8; m2++) {
                int mm = 8 * ms + m2;
                ull a2[4];
#pragma unroll
                for (int i = 0; i < 4; i++)     // 8B-strided lanes: 1 wf each
                    a2[i] = *(const ull*)&As[mm][2 * tx + 32 * i];
#pragma unroll
                for (int cc = 0; cc < 4; cc++) {
                    const float* xf = (const float*)&xr[cc][m2 >> 2];
                    float xv = xf[m2 & 3];
                    ull b2 = pack2(xv, xv);     // ALU pipe (idle)
#pragma unroll
                    for (int i = 0; i < 4; i++) ffma2(acc[i][cc], a2[i], b2);
                }
            }
        }
        __syncthreads();
    }

#pragma unroll
    for (int cc = 0; cc < 4; cc++) {
        int c = 4 * ty + cc;
#pragma unroll
        for (int i = 0; i < 4; i++) {
            float lo, hi;
            unpack2(lo, hi, acc[i][cc]);
            int n = n0 + 2 * tx + 32 * i;
            *(float2*)&y[(size_t)b * (CDIM * NDIM) + (size_t)c * NDIM + n] =
                make_float2(lo, hi);
        }
    }
}

// ---------------------------------------------------------------------------
// Launch. d_in[0] = x. d_out = [ y | attn ]. Graph-capturable, alloc-free.
// ---------------------------------------------------------------------------
extern "C" void kernel_launch(void* const* d_in, const int* in_sizes, int n_in,
                              void* d_out, int out_size) {
    (void)in_sizes; (void)n_in; (void)out_size;
    const float* x = (const float*)d_in[0];
    float* out  = (float*)d_out;
    float* y    = out;
    float* attn = out + Y_ELEMS;

    dim3 g1(NDIM / 128, NDIM / 128, BATCH);   // (32, 32, 8)
    scores_kernel<<<g1, 256>>>(x, attn);

    dim3 g2(NDIM, BATCH);                     // (4096, 8)
    softmax_kernel<<<g2, 128>>>(attn);

    dim3 g3(NDIM / 128, BATCH);               // (32, 8): ~one wave @ occ 2
    av_kernel<<<g3, 256>>>(x, attn, y);
}

// round 15
// speedup vs baseline: 1.1360x; 1.0006x over previous
#include <cuda_runtime.h>

// Problem: x [B=8, C=64, H=64, W=64], N = H*W = 4096
// out = [ y (B*C*N fp32) | attn (B*N*N fp32) ]
#define BATCH 8
#define CDIM  64
#define NDIM  4096
#define NN    (NDIM * NDIM)
#define Y_ELEMS (BATCH * CDIM * NDIM)

typedef unsigned long long ull;

// ---------------------------------------------------------------------------
// Packed f32x2 (sm_103a FFMA2 — 2x fp32 FMA throughput, PTX-only)
// ---------------------------------------------------------------------------
__device__ __forceinline__ ull pack2(float lo, float hi) {
    ull r; asm("mov.b64 %0, {%1, %2};" : "=l"(r) : "f"(lo), "f"(hi)); return r;
}
__device__ __forceinline__ void unpack2(float& lo, float& hi, ull v) {
    asm("mov.b64 {%0, %1}, %2;" : "=f"(lo), "=f"(hi) : "l"(v));
}
__device__ __forceinline__ void ffma2(ull& d, ull a, ull b) {
    asm("fma.rn.f32x2 %0, %1, %2, %0;" : "+l"(d) : "l"(a), "l"(b));
}

// ---------------------------------------------------------------------------
// K1: raw scores S[b][n][m] = sum_c x[b][c][n] * x[b][c][m]
// 128x128 tile, 256 threads (16x16), per-thread 8 rows x 8 cols.
// LDS budget per cl per thread: 2 LDS.128 (Ks: 8 cols = 4 reg-adjacent f32x2
// pairs) + 4 LDS.128 (Qd dup'd: 2 duplicated row-operands each) = 6 LDS for
// 32 FFMA2. Crossbar wavefronts/warp/cl: 8 vs 64 fma-pipe cycles -> fma-bound.
// ---------------------------------------------------------------------------
__global__ __launch_bounds__(256, 2)
void scores_kernel(const float* __restrict__ x, float* __restrict__ attn) {
    __shared__ float Qd[32][256];   // Q chunk duplicated: Qd[cl][2r]=(q,q)
    __shared__ float Ks[32][128];   // K chunk

    const int t  = threadIdx.x;
    const int tx = t & 15;          // cols: 4*tx + 64*u + {0..3}
    const int ty = t >> 4;          // rows: 4*ty + 64*v + {0..3}
    const int m0 = blockIdx.x * 128;
    const int n0 = blockIdx.y * 128;
    const int b  = blockIdx.z;
    const float* xb = x + (size_t)b * (CDIM * NDIM);

    ull acc[2][4][2][2];            // [v][rr][u][pair]
#pragma unroll
    for (int v = 0; v < 2; v++)
#pragma unroll
        for (int rr = 0; rr < 4; rr++)
#pragma unroll
            for (int u = 0; u < 2; u++) {
                acc[v][rr][u][0] = 0ULL;
                acc[v][rr][u][1] = 0ULL;
            }

    for (int cc = 0; cc < CDIM; cc += 32) {
        // 256 threads load 32x128 Q (dup-stored) + 32x128 K. Coalesced LDG.
#pragma unroll
        for (int k = 0; k < 16; k++) {
            int idx = t + k * 256;           // 0..4095
            int cl  = idx >> 7;
            int j   = idx & 127;
            float q = xb[(cc + cl) * NDIM + n0 + j];
            *(float2*)&Qd[cl][2 * j] = make_float2(q, q);
            Ks[cl][j] = xb[(cc + cl) * NDIM + m0 + j];
        }
        __syncthreads();

#pragma unroll
        for (int cl = 0; cl < 32; cl++) {
            // b-side: 8 cols as 2 LDS.128 -> 4 f32x2 pairs (reg-adjacent)
            float4 kv0 = *(const float4*)&Ks[cl][4 * tx];
            float4 kv1 = *(const float4*)&Ks[cl][4 * tx + 64];
            const ull* k0 = (const ull*)&kv0;
            const ull* k1 = (const ull*)&kv1;
#pragma unroll
            for (int v = 0; v < 2; v++) {
#pragma unroll
                for (int rp = 0; rp < 2; rp++) {
                    // a-side: LDS.128 on dup'd Qd -> 2 duplicated row operands
                    float4 qv = *(const float4*)&Qd[cl][8 * ty + 128 * v + 4 * rp];
                    const ull* qq = (const ull*)&qv;
#pragma unroll
                    for (int h = 0; h < 2; h++) {
                        int rr = 2 * rp + h;
                        ffma2(acc[v][rr][0][0], qq[h], k0[0]);
                        ffma2(acc[v][rr][0][1], qq[h], k0[1]);
                        ffma2(acc[v][rr][1][0], qq[h], k1[0]);
                        ffma2(acc[v][rr][1][1], qq[h], k1[1]);
                    }
                }
            }
        }
        __syncthreads();
    }

    float* arow = attn + (size_t)b * NN;
#pragma unroll
    for (int v = 0; v < 2; v++)
#pragma unroll
        for (int rr = 0; rr < 4; rr++) {
            int r = 4 * ty + 64 * v + rr;
            size_t base = (size_t)(n0 + r) * NDIM + m0;
#pragma unroll
            for (int u = 0; u < 2; u++) {
                float4 o;
                unpack2(o.x, o.y, acc[v][rr][u][0]);
                unpack2(o.z, o.w, acc[v][rr][u][1]);
                *(float4*)&arow[base + 4 * tx + 64 * u] = o;  // STG.128
            }
        }
}

// ---------------------------------------------------------------------------
// K2: in-place row softmax (proven, near streaming limit). Unchanged.
// ---------------------------------------------------------------------------
__global__ __launch_bounds__(128)
void softmax_kernel(float* __restrict__ attn) {
    const int n = blockIdx.x;
    const int b = blockIdx.y;
    float4* row = (float4*)(attn + (size_t)b * NN + (size_t)n * NDIM);
    const int t = threadIdx.x;

    float4 v[8];
    float m = -1e30f;
#pragma unroll
    for (int k = 0; k < 8; k++) {
        v[k] = row[t + 128 * k];
        m = fmaxf(m, fmaxf(fmaxf(v[k].x, v[k].y), fmaxf(v[k].z, v[k].w)));
    }
#pragma unroll
    for (int o = 16; o > 0; o >>= 1)
        m = fmaxf(m, __shfl_xor_sync(0xffffffffu, m, o));

    __shared__ float smax[4];
    __shared__ float ssum[4];
    const int warp = t >> 5, lane = t & 31;
    if (lane == 0) smax[warp] = m;
    __syncthreads();
    m = fmaxf(fmaxf(smax[0], smax[1]), fmaxf(smax[2], smax[3]));

    float s = 0.0f;
#pragma unroll
    for (int k = 0; k < 8; k++) {
        v[k].x = __expf(v[k].x - m);
        v[k].y = __expf(v[k].y - m);
        v[k].z = __expf(v[k].z - m);
        v[k].w = __expf(v[k].w - m);
        s += (v[k].x + v[k].y) + (v[k].z + v[k].w);
    }
#pragma unroll
    for (int o = 16; o > 0; o >>= 1)
        s += __shfl_xor_sync(0xffffffffu, s, o);
    if (lane == 0) ssum[warp] = s;
    __syncthreads();
    s = (ssum[0] + ssum[1]) + (ssum[2] + ssum[3]);

    const float inv = 1.0f / s;
#pragma unroll
    for (int k = 0; k < 8; k++) {
        v[k].x *= inv; v[k].y *= inv; v[k].z *= inv; v[k].w *= inv;
        row[t + 128 * k] = v[k];
    }
}

// ---------------------------------------------------------------------------
// K3: y[b][c][n] = sum_m attn[b][n][m] * x[b][c][m]
// 128 n x 64 c per CTA, 256 threads; per-thread 4 n-pairs x 4 c.
// X stored c-major Xt[c][m] (pitch 36 = 16B-aligned rows, conflict-free STS);
// each thread preloads its 4 c x 8 m into registers (LDS.128, broadcast wf),
// duplicates on the idle ALU pipe via pack2. LDS wf/mm drops 8 -> ~5.
// ---------------------------------------------------------------------------
__global__ __launch_bounds__(256, 2)
void av_kernel(const float* __restrict__ x, const float* __restrict__ attn,
               float* __restrict__ y) {
    __shared__ float As[32][130];   // attn tile transposed: As[m][n-row]
    __shared__ float Xt[64][36];    // X tile c-major: Xt[c][m]

    const int t  = threadIdx.x;
    const int tx = t & 15;          // n-pairs: 2*tx + 32*i
    const int ty = t >> 4;          // c: 4*ty + cc
    const int n0 = blockIdx.x * 128;
    const int b  = blockIdx.y;
    const float* xb = x + (size_t)b * (CDIM * NDIM);
    const float* ab = attn + (size_t)b * NN;

    ull acc[4][4];                  // [i: n-pair][cc: c]
#pragma unroll
    for (int i = 0; i < 4; i++)
#pragma unroll
        for (int cc = 0; cc < 4; cc++) acc[i][cc] = 0ULL;

    for (int m0 = 0; m0 < NDIM; m0 += 32) {
        // As[j][r] = attn[n0+r][m0+j] : coalesced LDG, mild STS conflict
#pragma unroll
        for (int kk = 0; kk < 16; kk++) {
            int idx = t + kk * 256;
            int r = idx >> 5;
            int j = idx & 31;
            As[j][r] = ab[(size_t)(n0 + r) * NDIM + m0 + j];
        }
        // Xt[c][j] = x[c][m0+j] : coalesced LDG, conflict-free STS (stride 1)
#pragma unroll
        for (int kk = 0; kk < 8; kk++) {
            int idx = t + kk * 256;
            int c = idx >> 5;
            int j = idx & 31;
            Xt[c][j] = xb[c * NDIM + m0 + j];
        }
        __syncthreads();

#pragma unroll
        for (int ms = 0; ms < 4; ms++) {        // 4 segments of 8 m
            // Preload this thread's 4 c-rows x 8 m into registers.
            float4 xr[4][2];
#pragma unroll
            for (int cc = 0; cc < 4; cc++) {
                xr[cc][0] = *(const float4*)&Xt[4 * ty + cc][8 * ms];
                xr[cc][1] = *(const float4*)&Xt[4 * ty + cc][8 * ms + 4];
            }
#pragma unroll
            for (int m2 = 0; m2 < 8; m2++) {
                int mm = 8 * ms + m2;
                ull a2[4];
#pragma unroll
                for (int i = 0; i < 4; i++)     // 8B-strided lanes: 1 wf each
                    a2[i] = *(const ull*)&As[mm][2 * tx + 32 * i];
#pragma unroll
                for (int cc = 0; cc < 4; cc++) {
                    const float* xf = (const float*)&xr[cc][m2 >> 2];
                    float xv = xf[m2 & 3];
                    ull b2 = pack2(xv, xv);     // ALU pipe (idle)
#pragma unroll
                    for (int i = 0; i < 4; i++) ffma2(acc[i][cc], a2[i], b2);
                }
            }
        }
        __syncthreads();
    }

#pragma unroll
    for (int cc = 0; cc < 4; cc++) {
        int c = 4 * ty + cc;
#pragma unroll
        for (int i = 0; i < 4; i++) {
            float lo, hi;
            unpack2(lo, hi, acc[i][cc]);
            int n = n0 + 2 * tx + 32 * i;
            *(float2*)&y[(size_t)b * (CDIM * NDIM) + (size_t)c * NDIM + n] =
                make_float2(lo, hi);
        }
    }
}

// ---------------------------------------------------------------------------
// Launch. d_in[0] = x. d_out = [ y | attn ]. Graph-capturable, alloc-free.
// ---------------------------------------------------------------------------
extern "C" void kernel_launch(void* const* d_in, const int* in_sizes, int n_in,
                              void* d_out, int out_size) {
    (void)in_sizes; (void)n_in; (void)out_size;
    const float* x = (const float*)d_in[0];
    float* out  = (float*)d_out;
    float* y    = out;
    float* attn = out + Y_ELEMS;

    dim3 g1(NDIM / 128, NDIM / 128, BATCH);   // (32, 32, 8)
    scores_kernel<<<g1, 256>>>(x, attn);

    dim3 g2(NDIM, BATCH);                     // (4096, 8)
    softmax_kernel<<<g2, 128>>>(attn);

    dim3 g3(NDIM / 128, BATCH);               // (32, 8): ~one wave @ occ 2
    av_kernel<<<g3, 256>>>(x, attn, y);
}